// round 4
// baseline (speedup 1.0000x reference)
#include <cuda_runtime.h>
#include <cstdint>

#define BATCHN 4096
#define NI 784
#define WID 16000
#define NHID 4
#define NCLS 10
#define W64 (BATCHN / 64)        // 64 words of 64 batch-bits each
#define GROUP (WID / NCLS)       // 1600 neurons per class

// L2-resident working set: packed input + ping-pong activation buffers.
__device__ uint64_t g_xp[(size_t)NI * W64];             // 401 KB
__device__ uint64_t g_h[2][(size_t)WID * W64];          // 2 x 8.2 MB

// Bool-encoding mode, detected at runtime from the x buffer:
//   0 = 1 byte per bool (uint8 nonzero)
//   1 = 4 bytes per bool (int32 0/1 or float32 0/1.0 -> word nonzero)
//   2 = 2 bytes per bool (bf16 0/1.0 -> half nonzero)
__device__ int g_mode;

__global__ void detect_mode_k(const uint32_t* __restrict__ x) {
    bool w32 = true, bf16 = true, u8 = true;
    for (int i = 0; i < 64; i++) {
        uint32_t w = x[i];
        if (!(w == 0u || w == 1u || w == 0x3F800000u)) w32 = false;
        uint32_t h0 = w & 0xFFFFu, h1 = w >> 16;
        if (!((h0 == 0u || h0 == 0x3F80u) && (h1 == 0u || h1 == 0x3F80u))) bf16 = false;
        if ((w & 0xFEFEFEFEu) != 0u) u8 = false;
    }
    g_mode = w32 ? 1 : (bf16 ? 2 : (u8 ? 0 : 1));
}

static __device__ __forceinline__ uint32_t read_bool(const void* __restrict__ p,
                                                     size_t e, int mode) {
    if (mode == 1) return ((const uint32_t*)p)[e] != 0u;
    if (mode == 0) return ((const uint8_t*)p)[e] != 0u;
    return ((const uint16_t*)p)[e] != 0u;
}

// ---------------------------------------------------------------------------
// Pack x[BATCH][NI] -> g_xp[i][w], bit j = sample w*64+j.
// ---------------------------------------------------------------------------
__global__ void pack_x_k(const void* __restrict__ x) {
    int t = blockIdx.x * blockDim.x + threadIdx.x;
    if (t >= NI * W64) return;
    int mode = g_mode;
    int w = t / NI;
    int i = t - w * NI;
    size_t base = (size_t)(w * 64) * NI + i;
    uint64_t acc = 0;
#pragma unroll
    for (int j = 0; j < 64; j++) {
        acc |= (uint64_t)read_bool(x, base + (size_t)j * NI, mode) << j;
    }
    g_xp[(size_t)i * W64 + w] = acc;
}

// ---------------------------------------------------------------------------
// Input layer: h0[n][w] = (xp[ia0[n]][w] ^ ma) & (xp[ib0[n]][w] ^ mb)
// ---------------------------------------------------------------------------
__global__ void layer0_k(const int* __restrict__ ia, const int* __restrict__ ib,
                         const void* __restrict__ ng) {
    int t = blockIdx.x * blockDim.x + threadIdx.x;
    if (t >= WID * W64) return;
    int mode = g_mode;
    int n = t >> 6;
    int w = t & 63;
    uint64_t ma = 0ULL - (uint64_t)read_bool(ng, 2 * n, mode);
    uint64_t mb = 0ULL - (uint64_t)read_bool(ng, 2 * n + 1, mode);
    uint64_t va = g_xp[(size_t)ia[n] * W64 + w] ^ ma;
    uint64_t vb = g_xp[(size_t)ib[n] * W64 + w] ^ mb;
    g_h[0][(size_t)n * W64 + w] = va & vb;
}

// ---------------------------------------------------------------------------
// Hidden layer: g_h[src^1][n][w] = gate(g_h[src][ia[n]][w], g_h[src][ib[n]][w])
// ---------------------------------------------------------------------------
__global__ void layerh_k(const int* __restrict__ ia, const int* __restrict__ ib,
                         const void* __restrict__ ng, size_t ng_off, int src) {
    int t = blockIdx.x * blockDim.x + threadIdx.x;
    if (t >= WID * W64) return;
    int mode = g_mode;
    int n = t >> 6;
    int w = t & 63;
    const uint64_t* __restrict__ hs = g_h[src];
    uint64_t* __restrict__ hd = g_h[src ^ 1];
    uint64_t ma = 0ULL - (uint64_t)read_bool(ng, ng_off + 2 * n, mode);
    uint64_t mb = 0ULL - (uint64_t)read_bool(ng, ng_off + 2 * n + 1, mode);
    uint64_t va = hs[(size_t)ia[n] * W64 + w] ^ ma;
    uint64_t vb = hs[(size_t)ib[n] * W64 + w] ^ mb;
    hd[(size_t)n * W64 + w] = va & vb;
}

// ---------------------------------------------------------------------------
// GroupSum: out[b][c] = popcount of bit b over class-c group (1600 neurons).
// OUTPUT IS WRITTEN AS FLOAT32 (harness canonical output dtype).
// ---------------------------------------------------------------------------
__global__ void reduce_k(float* __restrict__ out, int src) {
    int t = blockIdx.x * blockDim.x + threadIdx.x;
    if (t >= NCLS * BATCHN) return;
    int c = t / BATCHN;
    int b = t - c * BATCHN;
    int w = b >> 6;
    int bit = b & 63;
    const uint64_t* __restrict__ hp = g_h[src] + (size_t)c * GROUP * W64 + w;
    int cnt = 0;
#pragma unroll 16
    for (int n = 0; n < GROUP; n++) {
        cnt += (int)((hp[(size_t)n * W64] >> bit) & 1ULL);
    }
    out[b * NCLS + c] = (float)cnt;
}

// ---------------------------------------------------------------------------
// Bind inputs BY ELEMENT COUNT (robust to metadata ordering):
//   x: 3,211,264   idx_a0/idx_b0: 16,000 (a first)   neg0: 32,000
//   idx_a/idx_b: 64,000 (a first)   neg: 128,000
// Output: float32 [BATCH, NCLS]
// ---------------------------------------------------------------------------
extern "C" void kernel_launch(void* const* d_in, const int* in_sizes, int n_in,
                              void* d_out, int out_size) {
    const void* x = nullptr;
    const int *ia0 = nullptr, *ib0 = nullptr, *iah = nullptr, *ibh = nullptr;
    const void *ng0 = nullptr, *ngh = nullptr;

    for (int i = 0; i < n_in; i++) {
        int sz = in_sizes[i];
        if (sz == BATCHN * NI) {
            x = d_in[i];
        } else if (sz == WID) {
            if (!ia0) ia0 = (const int*)d_in[i]; else ib0 = (const int*)d_in[i];
        } else if (sz == WID * 2) {
            ng0 = d_in[i];
        } else if (sz == NHID * WID) {
            if (!iah) iah = (const int*)d_in[i]; else ibh = (const int*)d_in[i];
        } else if (sz == NHID * WID * 2) {
            ngh = d_in[i];
        }
    }
    float* out = (float*)d_out;

    const int TB = 256;

    detect_mode_k<<<1, 1>>>((const uint32_t*)x);
    pack_x_k<<<(NI * W64 + TB - 1) / TB, TB>>>(x);
    layer0_k<<<(WID * W64 + TB - 1) / TB, TB>>>(ia0, ib0, ng0);

    // 4 hidden layers, ping-pong: 0->1->0->1->0 (final result in buffer 0)
    for (int k = 0; k < NHID; k++) {
        layerh_k<<<(WID * W64 + TB - 1) / TB, TB>>>(
            iah + (size_t)k * WID,
            ibh + (size_t)k * WID,
            ngh, (size_t)k * WID * 2,
            k & 1);
    }

    reduce_k<<<(NCLS * BATCHN + TB - 1) / TB, TB>>>(out, 0);
}

// round 6
// speedup vs baseline: 2.1418x; 2.1418x over previous
#include <cuda_runtime.h>
#include <cstdint>

#define BATCHN 4096
#define NI 784
#define WID 16000
#define NHID 4
#define NCLS 10
#define W64 (BATCHN / 64)        // 64 u64 words per neuron (64 batch bits each)
#define GROUP (WID / NCLS)       // 1600 neurons per class
#define RCHUNK 8                 // reduce: chunks per class group
#define CN (GROUP / RCHUNK)      // 200 neurons per reduce chunk

// L2-resident working set: packed input + ping-pong activation buffers.
// NOTE: these are referenced ONLY from device code (host passes selectors).
__device__ uint64_t g_xp[(size_t)NI * W64];             // 401 KB
__device__ uint64_t g_h[2][(size_t)WID * W64];          // 2 x 8.2 MB

// Bool-encoding mode (runtime-detected): 0=u8, 1=4-byte word, 2=2-byte half.
__device__ int g_mode;

// Buffer selector resolved in device code: 0 = g_xp, 1 = g_h[0], 2 = g_h[1].
static __device__ __forceinline__ uint64_t* bufptr(int s) {
    return s == 0 ? g_xp : g_h[s - 1];
}

static __device__ __forceinline__ uint32_t read_bool(const void* __restrict__ p,
                                                     size_t e, int mode) {
    if (mode == 1) return ((const uint32_t*)p)[e] != 0u;
    if (mode == 0) return ((const uint8_t*)p)[e] != 0u;
    return ((const uint16_t*)p)[e] != 0u;
}

// ---------------------------------------------------------------------------
// prep_k: zero the output (it is poisoned) AND detect bool encoding (thread 0).
// ---------------------------------------------------------------------------
__global__ void prep_k(const uint32_t* __restrict__ x, float* __restrict__ out) {
    int t = blockIdx.x * blockDim.x + threadIdx.x;
    if (t < NCLS * BATCHN) out[t] = 0.0f;
    if (t == 0) {
        bool w32 = true, bf16 = true, u8 = true;
        for (int i = 0; i < 64; i++) {
            uint32_t w = x[i];
            if (!(w == 0u || w == 1u || w == 0x3F800000u)) w32 = false;
            uint32_t h0 = w & 0xFFFFu, h1 = w >> 16;
            if (!((h0 == 0u || h0 == 0x3F80u) && (h1 == 0u || h1 == 0x3F80u))) bf16 = false;
            if ((w & 0xFEFEFEFEu) != 0u) u8 = false;
        }
        g_mode = w32 ? 1 : (bf16 ? 2 : (u8 ? 0 : 1));
    }
}

// ---------------------------------------------------------------------------
// pack_x_k: tiled transpose through shared memory. Block = (word w, 64-input
// tile). Loads of x are fully coalesced; 64 threads then assemble u64 words.
// ---------------------------------------------------------------------------
__global__ void pack_x_k(const void* __restrict__ x) {
    __shared__ uint8_t tile[64][65];
    int mode = g_mode;
    int w = blockIdx.x;                 // 0..63
    int i0 = blockIdx.y * 64;           // input tile base
    int tx = threadIdx.x & 63;
    int ty = threadIdx.x >> 6;          // 0..3
#pragma unroll
    for (int r = 0; r < 16; r++) {
        int j = r * 4 + ty;             // sample within word
        int i = i0 + tx;
        uint8_t v = 0;
        if (i < NI) v = (uint8_t)read_bool(x, (size_t)(w * 64 + j) * NI + i, mode);
        tile[j][tx] = v;
    }
    __syncthreads();
    if (threadIdx.x < 64) {
        int i = i0 + (int)threadIdx.x;
        if (i < NI) {
            uint64_t acc = 0;
#pragma unroll
            for (int j = 0; j < 64; j++)
                acc |= (uint64_t)tile[j][threadIdx.x] << j;
            g_xp[(size_t)i * W64 + w] = acc;
        }
    }
}

// ---------------------------------------------------------------------------
// layer_k: one thread = 4 u64 words of one neuron (two LDG.128 per operand).
// 16 threads/neuron; warp covers 2 neurons -> ia/ib/neg near-uniform loads;
// gathers are coalesced 512B rows. Buffers resolved device-side by selector.
// ---------------------------------------------------------------------------
__global__ void layer_k(int srcsel, int dstsel,
                        const int* __restrict__ ia, const int* __restrict__ ib,
                        const void* __restrict__ ng, size_t ng_off) {
    int t = blockIdx.x * blockDim.x + threadIdx.x;
    if (t >= WID * (W64 / 4)) return;
    const uint64_t* __restrict__ src = bufptr(srcsel);
    uint64_t* __restrict__ dst = bufptr(dstsel);
    int mode = g_mode;
    int n = t >> 4;
    int q = t & 15;
    uint64_t ma = 0ULL - (uint64_t)read_bool(ng, ng_off + 2 * n, mode);
    uint64_t mb = 0ULL - (uint64_t)read_bool(ng, ng_off + 2 * n + 1, mode);
    const ulonglong2* __restrict__ pa =
        (const ulonglong2*)(src + (size_t)ia[n] * W64) + 2 * q;
    const ulonglong2* __restrict__ pb =
        (const ulonglong2*)(src + (size_t)ib[n] * W64) + 2 * q;
    ulonglong2 a0 = pa[0], a1 = pa[1];
    ulonglong2 b0 = pb[0], b1 = pb[1];
    ulonglong2 r0, r1;
    r0.x = (a0.x ^ ma) & (b0.x ^ mb);
    r0.y = (a0.y ^ ma) & (b0.y ^ mb);
    r1.x = (a1.x ^ ma) & (b1.x ^ mb);
    r1.y = (a1.y ^ ma) & (b1.y ^ mb);
    ulonglong2* __restrict__ pd = (ulonglong2*)(dst + (size_t)n * W64) + 2 * q;
    pd[0] = r0;
    pd[1] = r1;
}

// ---------------------------------------------------------------------------
// reduce_k: warp per (class, word, 200-neuron chunk). Lanes share each u64
// word (broadcast load); lane l accumulates bits l and l+32, then atomically
// adds the (small, exact) integer counts into the float output.
// ---------------------------------------------------------------------------
__global__ void reduce_k(float* __restrict__ out, int src) {
    int gw = (blockIdx.x * blockDim.x + threadIdx.x) >> 5;
    int lane = threadIdx.x & 31;
    if (gw >= NCLS * W64 * RCHUNK) return;
    int c = gw / (W64 * RCHUNK);
    int rem = gw - c * (W64 * RCHUNK);
    int w = rem / RCHUNK;
    int ch = rem - w * RCHUNK;
    const uint64_t* __restrict__ hp =
        g_h[src] + ((size_t)c * GROUP + (size_t)ch * CN) * W64 + w;
    int c0 = 0, c1 = 0;
#pragma unroll 8
    for (int n = 0; n < CN; n++) {
        uint64_t v = hp[(size_t)n * W64];
        c0 += (int)((v >> lane) & 1ULL);
        c1 += (int)((v >> (lane + 32)) & 1ULL);
    }
    int b0 = w * 64 + lane;
    atomicAdd(&out[(size_t)b0 * NCLS + c], (float)c0);
    atomicAdd(&out[(size_t)(b0 + 32) * NCLS + c], (float)c1);
}

// ---------------------------------------------------------------------------
// Bind inputs BY ELEMENT COUNT (robust to metadata ordering):
//   x: 3,211,264   idx_a0/idx_b0: 16,000 (a first)   neg0: 32,000
//   idx_a/idx_b: 64,000 (a first)   neg: 128,000
// Output: float32 [BATCH, NCLS]
// ---------------------------------------------------------------------------
extern "C" void kernel_launch(void* const* d_in, const int* in_sizes, int n_in,
                              void* d_out, int out_size) {
    const void* x = nullptr;
    const int *ia0 = nullptr, *ib0 = nullptr, *iah = nullptr, *ibh = nullptr;
    const void *ng0 = nullptr, *ngh = nullptr;

    for (int i = 0; i < n_in; i++) {
        int sz = in_sizes[i];
        if (sz == BATCHN * NI) {
            x = d_in[i];
        } else if (sz == WID) {
            if (!ia0) ia0 = (const int*)d_in[i]; else ib0 = (const int*)d_in[i];
        } else if (sz == WID * 2) {
            ng0 = d_in[i];
        } else if (sz == NHID * WID) {
            if (!iah) iah = (const int*)d_in[i]; else ibh = (const int*)d_in[i];
        } else if (sz == NHID * WID * 2) {
            ngh = d_in[i];
        }
    }
    float* out = (float*)d_out;

    const int TB = 256;

    prep_k<<<(NCLS * BATCHN + TB - 1) / TB, TB>>>((const uint32_t*)x, out);

    dim3 pg(W64, (NI + 63) / 64);
    pack_x_k<<<pg, TB>>>(x);

    const int LT = WID * (W64 / 4);     // 256000 threads per layer
    // input layer: src = g_xp (sel 0), dst = g_h[0] (sel 1)
    layer_k<<<(LT + TB - 1) / TB, TB>>>(0, 1, ia0, ib0, ng0, 0);

    // 4 hidden layers, ping-pong: h0->h1->h0->h1->h0 (final in g_h[0])
    for (int k = 0; k < NHID; k++) {
        layer_k<<<(LT + TB - 1) / TB, TB>>>(
            1 + (k & 1), 1 + ((k & 1) ^ 1),
            iah + (size_t)k * WID,
            ibh + (size_t)k * WID,
            ngh, (size_t)k * WID * 2);
    }

    const int RT = NCLS * W64 * RCHUNK * 32;   // 163840 threads
    reduce_k<<<(RT + TB - 1) / TB, TB>>>(out, 0);
}